// round 1
// baseline (speedup 1.0000x reference)
#include <cuda_runtime.h>
#include <math.h>
#include <stdint.h>

// Problem constants
#define B_  8
#define T_  2048
#define D_  1024
#define FF_ 4096
#define E_  8
#define K_  2

// GEMM tiling
#define BM 128
#define BN 128
#define BK 16
#define SA_LD (BM + 4)   // padded smem leading dims
#define SB_LD (BN + 4)

// Scratch (static device globals: allocation-free per harness rules)
__device__ float g_pooled[B_ * D_];
__device__ int   g_idx[B_ * K_];
__device__ float g_w[B_ * K_];
__device__ float g_h[134217728];   // B*K*T*FF = 8*2*2048*4096 floats (512 MB)

// ---------------------------------------------------------------------------
// Routing
// ---------------------------------------------------------------------------
__global__ void pool_kernel(const float* __restrict__ x) {
    int b = blockIdx.y;
    int d = blockIdx.x * 256 + threadIdx.x;
    const float* p = x + (size_t)b * T_ * D_ + d;
    float s = 0.0f;
    for (int t = 0; t < T_; ++t) s += p[(size_t)t * D_];
    g_pooled[b * D_ + d] = s * (1.0f / (float)T_);
}

__global__ void route_kernel(const float* __restrict__ Wr) {
    __shared__ float lg[B_ * E_];
    int tid = threadIdx.x;
    if (tid < B_ * E_) {
        int b = tid / E_, e = tid % E_;
        float s = 0.0f;
        for (int d = 0; d < D_; ++d) s += g_pooled[b * D_ + d] * Wr[d * E_ + e];
        lg[tid] = s;
    }
    __syncthreads();
    if (tid < B_) {
        float best = -1e30f; int bi = 0;
        for (int e = 0; e < E_; ++e) {
            float v = lg[tid * E_ + e];
            if (v > best) { best = v; bi = e; }
        }
        float sec = -1e30f; int si = 0;
        for (int e = 0; e < E_; ++e) {
            if (e == bi) continue;
            float v = lg[tid * E_ + e];
            if (v > sec) { sec = v; si = e; }
        }
        // softmax over {best, sec}
        float e1 = expf(sec - best);
        float inv = 1.0f / (1.0f + e1);
        g_idx[tid * K_ + 0] = bi;
        g_idx[tid * K_ + 1] = si;
        g_w[tid * K_ + 0] = inv;
        g_w[tid * K_ + 1] = e1 * inv;
    }
}

// ---------------------------------------------------------------------------
// TF32 mma.sync helpers
// ---------------------------------------------------------------------------
__device__ __forceinline__ uint32_t f2tf(float f) {
    uint32_t u;
    asm("cvt.rna.tf32.f32 %0, %1;" : "=r"(u) : "f"(f));
    return u;
}

__device__ __forceinline__ void mma_tf32(float c[4], const uint32_t a[4], const uint32_t b[2]) {
    asm volatile(
        "mma.sync.aligned.m16n8k8.row.col.f32.tf32.tf32.f32 "
        "{%0,%1,%2,%3},{%4,%5,%6,%7},{%8,%9},{%0,%1,%2,%3};\n"
        : "+f"(c[0]), "+f"(c[1]), "+f"(c[2]), "+f"(c[3])
        : "r"(a[0]), "r"(a[1]), "r"(a[2]), "r"(a[3]), "r"(b[0]), "r"(b[1]));
}

// Accumulate C[128,128] += A[128,K] * B[K,128] (row-major A and B).
// A pre-offset to block row 0 of the tile; B pre-offset to block col 0.
// 256 threads, 8 warps as 4(M) x 2(N), warp tile 32x64.
__device__ __forceinline__ void gemm_accum(
    float acc[2][8][4],
    const float* __restrict__ A, const float* __restrict__ Bm,
    int ldA, int ldB, int kIters,
    float* sA, float* sB)
{
    int tid  = threadIdx.x;
    int lane = tid & 31, warp = tid >> 5;
    int g    = lane >> 2, tig = lane & 3;
    int wm   = (warp & 3) * 32;
    int wn   = (warp >> 2) * 64;
    int ar   = tid >> 2;          // 0..63  (A row)
    int akq  = (tid & 3) * 4;     // A k-quad offset
    int bkr  = tid >> 5;          // 0..7   (B k row)
    int bnq  = (tid & 31) * 4;    // B n-quad offset

    for (int kt = 0; kt < kIters; ++kt) {
        // A tile: [BM][BK] -> smem transposed sA[k][m]
        #pragma unroll
        for (int h = 0; h < 2; ++h) {
            int row = ar + h * 64;
            float4 v = *(const float4*)(A + (size_t)row * ldA + kt * BK + akq);
            sA[(akq + 0) * SA_LD + row] = v.x;
            sA[(akq + 1) * SA_LD + row] = v.y;
            sA[(akq + 2) * SA_LD + row] = v.z;
            sA[(akq + 3) * SA_LD + row] = v.w;
        }
        // B tile: [BK][BN] -> smem sB[k][n]
        #pragma unroll
        for (int h = 0; h < 2; ++h) {
            int kr = bkr + h * 8;
            float4 v = *(const float4*)(Bm + (size_t)(kt * BK + kr) * ldB + bnq);
            *(float4*)(sB + kr * SB_LD + bnq) = v;
        }
        __syncthreads();

        #pragma unroll
        for (int ks = 0; ks < 2; ++ks) {
            int kb = ks * 8;
            uint32_t af[2][4];
            uint32_t bf[8][2];
            #pragma unroll
            for (int mt = 0; mt < 2; ++mt) {
                int r = wm + mt * 16 + g;
                af[mt][0] = f2tf(sA[(kb + tig)     * SA_LD + r]);
                af[mt][1] = f2tf(sA[(kb + tig)     * SA_LD + r + 8]);
                af[mt][2] = f2tf(sA[(kb + tig + 4) * SA_LD + r]);
                af[mt][3] = f2tf(sA[(kb + tig + 4) * SA_LD + r + 8]);
            }
            #pragma unroll
            for (int nt = 0; nt < 8; ++nt) {
                int c = wn + nt * 8 + g;
                bf[nt][0] = f2tf(sB[(kb + tig)     * SB_LD + c]);
                bf[nt][1] = f2tf(sB[(kb + tig + 4) * SB_LD + c]);
            }
            #pragma unroll
            for (int mt = 0; mt < 2; ++mt)
                #pragma unroll
                for (int nt = 0; nt < 8; ++nt)
                    mma_tf32(acc[mt][nt], af[mt], bf[nt]);
        }
        __syncthreads();
    }
}

// ---------------------------------------------------------------------------
// GEMM1: h[b,k] = w * gelu(x[b] @ W1[e] + b1[e])
// grid: (FF/BN, T/BM, B*K)
// ---------------------------------------------------------------------------
__global__ void __launch_bounds__(256) gemm1_kernel(
    const float* __restrict__ x, const float* __restrict__ W1,
    const float* __restrict__ b1)
{
    __shared__ float sA[BK * SA_LD];
    __shared__ float sB[BK * SB_LD];

    int bz = blockIdx.z;           // b*K + k
    int b  = bz >> 1;
    int e  = g_idx[bz];
    float w = g_w[bz];

    const float* A  = x  + (size_t)b * T_ * D_ + (size_t)blockIdx.y * BM * D_;
    const float* Bm = W1 + (size_t)e * D_ * FF_ + (size_t)blockIdx.x * BN;

    float acc[2][8][4];
    #pragma unroll
    for (int i = 0; i < 2; ++i)
        #pragma unroll
        for (int j = 0; j < 8; ++j)
            #pragma unroll
            for (int l = 0; l < 4; ++l) acc[i][j][l] = 0.0f;

    gemm_accum(acc, A, Bm, D_, FF_, D_ / BK, sA, sB);

    // Epilogue: bias + exact gelu + pre-scale by routing weight
    int tid  = threadIdx.x;
    int lane = tid & 31, warp = tid >> 5;
    int g    = lane >> 2, tig = lane & 3;
    int wm   = (warp & 3) * 32;
    int wn   = (warp >> 2) * 64;

    const float* bias = b1 + (size_t)e * FF_ + (size_t)blockIdx.x * BN;
    float* H = g_h + (size_t)bz * T_ * FF_ + (size_t)blockIdx.y * BM * FF_
                   + (size_t)blockIdx.x * BN;

    #pragma unroll
    for (int mt = 0; mt < 2; ++mt) {
        #pragma unroll
        for (int nt = 0; nt < 8; ++nt) {
            #pragma unroll
            for (int i = 0; i < 4; ++i) {
                int r = wm + mt * 16 + g + ((i >> 1) << 3);
                int c = wn + nt * 8 + tig * 2 + (i & 1);
                float v = acc[mt][nt][i] + bias[c];
                // exact GELU (erf form)
                v = 0.5f * v * (1.0f + erff(v * 0.70710678118654752440f));
                H[(size_t)r * FF_ + c] = w * v;
            }
        }
    }
}

// ---------------------------------------------------------------------------
// GEMM2: out[b] = sum_k h[b,k] @ W2[e_k] + sum_k w_k * b2[e_k]
// grid: (D/BN, T/BM, B)
// ---------------------------------------------------------------------------
__global__ void __launch_bounds__(256) gemm2_kernel(
    const float* __restrict__ W2, const float* __restrict__ b2,
    float* __restrict__ out)
{
    __shared__ float sA[BK * SA_LD];
    __shared__ float sB[BK * SB_LD];

    int b = blockIdx.z;

    float acc[2][8][4];
    #pragma unroll
    for (int i = 0; i < 2; ++i)
        #pragma unroll
        for (int j = 0; j < 8; ++j)
            #pragma unroll
            for (int l = 0; l < 4; ++l) acc[i][j][l] = 0.0f;

    for (int k = 0; k < K_; ++k) {
        int bz = b * K_ + k;
        int e  = g_idx[bz];
        const float* A  = g_h + (size_t)bz * T_ * FF_ + (size_t)blockIdx.y * BM * FF_;
        const float* Bm = W2  + (size_t)e * FF_ * D_ + (size_t)blockIdx.x * BN;
        gemm_accum(acc, A, Bm, FF_, D_, FF_ / BK, sA, sB);
    }

    int tid  = threadIdx.x;
    int lane = tid & 31, warp = tid >> 5;
    int g    = lane >> 2, tig = lane & 3;
    int wm   = (warp & 3) * 32;
    int wn   = (warp >> 2) * 64;

    int e0 = g_idx[b * K_ + 0], e1 = g_idx[b * K_ + 1];
    float w0 = g_w[b * K_ + 0], w1 = g_w[b * K_ + 1];
    const float* bias0 = b2 + (size_t)e0 * D_ + (size_t)blockIdx.x * BN;
    const float* bias1 = b2 + (size_t)e1 * D_ + (size_t)blockIdx.x * BN;

    float* O = out + (size_t)b * T_ * D_ + (size_t)blockIdx.y * BM * D_
                   + (size_t)blockIdx.x * BN;

    #pragma unroll
    for (int mt = 0; mt < 2; ++mt) {
        #pragma unroll
        for (int nt = 0; nt < 8; ++nt) {
            #pragma unroll
            for (int i = 0; i < 4; ++i) {
                int r = wm + mt * 16 + g + ((i >> 1) << 3);
                int c = wn + nt * 8 + tig * 2 + (i & 1);
                float cb = w0 * bias0[c] + w1 * bias1[c];
                O[(size_t)r * D_ + c] = acc[mt][nt][i] + cb;
            }
        }
    }
}

// ---------------------------------------------------------------------------
// Launch
// ---------------------------------------------------------------------------
extern "C" void kernel_launch(void* const* d_in, const int* in_sizes, int n_in,
                              void* d_out, int out_size) {
    (void)in_sizes; (void)n_in; (void)out_size;
    const float* x  = (const float*)d_in[0];
    const float* Wr = (const float*)d_in[1];
    const float* W1 = (const float*)d_in[2];
    const float* b1 = (const float*)d_in[3];
    const float* W2 = (const float*)d_in[4];
    const float* b2 = (const float*)d_in[5];
    float* out = (float*)d_out;

    pool_kernel<<<dim3(D_ / 256, B_), 256>>>(x);
    route_kernel<<<1, 64>>>(Wr);
    gemm1_kernel<<<dim3(FF_ / BN, T_ / BM, B_ * K_), 256>>>(x, W1, b1);
    gemm2_kernel<<<dim3(D_ / BN, T_ / BM, B_), 256>>>(W2, b2, out);
}

// round 3
// speedup vs baseline: 1.6778x; 1.6778x over previous
#include <cuda_runtime.h>
#include <math.h>
#include <stdint.h>

// Problem constants
#define B_  8
#define T_  2048
#define D_  1024
#define FF_ 4096
#define E_  8
#define K_  2

// GEMM tiling
#define BM 256
#define BN 128
#define KC 32
#define NSTAGE 4
#define NTH 256

#define A_ST_BYTES (BM * KC * 4)              // 32KB
#define B_ST_BYTES (BN * KC * 4)              // 16KB
#define ST_BYTES   (A_ST_BYTES + B_ST_BYTES)  // 48KB
#define SMEM_TOTAL (NSTAGE * ST_BYTES)        // 192KB

// ---------------------------------------------------------------------------
// Device-global scratch (allocation-free)
// ---------------------------------------------------------------------------
__device__ float g_pooled[B_ * D_];
__device__ int   g_idx[B_ * K_];
__device__ float g_w[B_ * K_];
__device__ __align__(256) float g_xt[B_ * T_ * D_];                // x, tf32, k-permuted
__device__ __align__(256) float g_w1t[(size_t)E_ * FF_ * D_];      // [E][FF][Dperm]
__device__ __align__(256) float g_w2t[(size_t)E_ * D_ * FF_];      // [E][D][FFperm]
__device__ __align__(256) float g_h[(size_t)B_ * K_ * T_ * FF_];   // h, tf32, FF-permuted

// ---------------------------------------------------------------------------
// Helpers
// ---------------------------------------------------------------------------
__device__ __forceinline__ uint32_t smem_u32(const void* p) {
    uint32_t a;
    asm("{ .reg .u64 t; cvta.to.shared.u64 t, %1; cvt.u32.u64 %0, t; }"
        : "=r"(a) : "l"(p));
    return a;
}

__device__ __forceinline__ float tf32r(float f) {
    uint32_t u;
    asm("cvt.rna.tf32.f32 %0, %1;" : "=r"(u) : "f"(f));
    return __uint_as_float(u);
}

// position of k-index c (0..7) in permuted order [0,4,1,5,2,6,3,7]
__device__ __host__ __forceinline__ int pos3(int c) {
    return ((c & 3) << 1) | (c >> 2);
}

__device__ __forceinline__ void cp16(uint32_t dst, const void* src) {
    asm volatile("cp.async.cg.shared.global [%0], [%1], 16;" :: "r"(dst), "l"(src));
}
__device__ __forceinline__ void cp_commit() {
    asm volatile("cp.async.commit_group;" ::: "memory");
}
__device__ __forceinline__ void cp_wait2() {
    asm volatile("cp.async.wait_group 2;" ::: "memory");
}

__device__ __forceinline__ void lds64(uint32_t& x, uint32_t& y, uint32_t a) {
    asm volatile("ld.shared.v2.b32 {%0,%1}, [%2];" : "=r"(x), "=r"(y) : "r"(a));
}

__device__ __forceinline__ void mma_tf32(float c[4], const uint32_t a[4], const uint32_t b[2]) {
    asm volatile(
        "mma.sync.aligned.m16n8k8.row.col.f32.tf32.tf32.f32 "
        "{%0,%1,%2,%3},{%4,%5,%6,%7},{%8,%9},{%0,%1,%2,%3};\n"
        : "+f"(c[0]), "+f"(c[1]), "+f"(c[2]), "+f"(c[3])
        : "r"(a[0]), "r"(a[1]), "r"(a[2]), "r"(a[3]), "r"(b[0]), "r"(b[1]));
}

// ---------------------------------------------------------------------------
// Routing
// ---------------------------------------------------------------------------
__global__ void pool_kernel(const float* __restrict__ x) {
    int b = blockIdx.y;
    int d = blockIdx.x * 256 + threadIdx.x;
    const float* p = x + (size_t)b * T_ * D_ + d;
    float s = 0.0f;
    for (int t = 0; t < T_; ++t) s += p[(size_t)t * D_];
    g_pooled[b * D_ + d] = s * (1.0f / (float)T_);
}

__global__ void route_kernel(const float* __restrict__ Wr) {
    __shared__ float lg[B_ * E_];
    int tid = threadIdx.x;
    if (tid < B_ * E_) {
        int b = tid / E_, e = tid % E_;
        float s = 0.0f;
        for (int d = 0; d < D_; ++d) s += g_pooled[b * D_ + d] * Wr[d * E_ + e];
        lg[tid] = s;
    }
    __syncthreads();
    if (tid < B_) {
        float best = -1e30f; int bi = 0;
        for (int e = 0; e < E_; ++e) {
            float v = lg[tid * E_ + e];
            if (v > best) { best = v; bi = e; }
        }
        float sec = -1e30f; int si = 0;
        for (int e = 0; e < E_; ++e) {
            if (e == bi) continue;
            float v = lg[tid * E_ + e];
            if (v > sec) { sec = v; si = e; }
        }
        float e1 = expf(sec - best);
        float inv = 1.0f / (1.0f + e1);
        g_idx[tid * K_ + 0] = bi;
        g_idx[tid * K_ + 1] = si;
        g_w[tid * K_ + 0] = inv;
        g_w[tid * K_ + 1] = e1 * inv;
    }
}

// ---------------------------------------------------------------------------
// Prep: tf32 round + k-permute (and transpose for weights)
// ---------------------------------------------------------------------------
__global__ void convert_x_kernel(const float* __restrict__ x) {
    size_t gi = (size_t)blockIdx.x * NTH + threadIdx.x;   // one k8 group per thread
    const float4* p = (const float4*)(x + gi * 8);
    float4 v0 = p[0], v1 = p[1];
    float in[8] = {v0.x, v0.y, v0.z, v0.w, v1.x, v1.y, v1.z, v1.w};
    float o[8];
    #pragma unroll
    for (int c = 0; c < 8; ++c) o[pos3(c)] = tf32r(in[c]);
    float4* q = (float4*)(g_xt + gi * 8);
    q[0] = make_float4(o[0], o[1], o[2], o[3]);
    q[1] = make_float4(o[4], o[5], o[6], o[7]);
}

// src [z][R][C] -> dst [z][C][Rperm], tf32-rounded
__device__ __forceinline__ void transpose_body(const float* __restrict__ src,
                                               float* __restrict__ dst,
                                               int R, int C) {
    __shared__ float t[32][33];
    int z = blockIdx.z;
    const float* s = src + (size_t)z * R * C;
    int c0 = blockIdx.x * 32, r0 = blockIdx.y * 32;
    int tx = threadIdx.x, ty = threadIdx.y;
    #pragma unroll
    for (int j = 0; j < 32; j += 8)
        t[ty + j][tx] = s[(size_t)(r0 + ty + j) * C + c0 + tx];
    __syncthreads();
    size_t ob = (size_t)z * R * C;
    int rp = r0 + (tx & ~7) + pos3(tx & 7);   // permuted inner (k) index
    #pragma unroll
    for (int j = 0; j < 32; j += 8) {
        float v = t[tx][ty + j];
        dst[ob + (size_t)(c0 + ty + j) * R + rp] = tf32r(v);
    }
}

__global__ void transpose_w1_kernel(const float* __restrict__ W1) {
    transpose_body(W1, g_w1t, D_, FF_);   // [E][D][FF] -> [E][FF][Dperm]
}
__global__ void transpose_w2_kernel(const float* __restrict__ W2) {
    transpose_body(W2, g_w2t, FF_, D_);   // [E][FF][D] -> [E][D][FFperm]
}

// ---------------------------------------------------------------------------
// GEMM core: 4-stage cp.async pipeline, tf32 mma.sync
// CTA tile 256x128, 8 warps in 4(M)x2(N), warp tile 64x64.
// smem tiles: A [256 rows][32 k] (128B rows), B [128][32]; 16B chunks
// swizzled with chunk ^= (row&3)<<1. k within each 8-group is pre-permuted
// in gmem so tf32 fragment pairs (k, k+4) are adjacent -> LDS.64.
// ---------------------------------------------------------------------------
__device__ __forceinline__ void load_stage(uint32_t stbase,
                                           const float* __restrict__ A,
                                           const float* __restrict__ Bp,
                                           int k0, int ldA, int ldB, int tid) {
    uint32_t aB = stbase, bB = stbase + A_ST_BYTES;
    #pragma unroll
    for (int j = 0; j < 8; ++j) {               // A: 2048 16B-chunks / 256 thr
        int i = tid + j * NTH;
        int r = i >> 3, c = i & 7;
        uint32_t d = aB + r * 128 + ((c ^ ((r & 3) << 1)) << 4);
        cp16(d, A + (size_t)r * ldA + k0 + c * 4);
    }
    #pragma unroll
    for (int j = 0; j < 4; ++j) {               // B: 1024 chunks
        int i = tid + j * NTH;
        int r = i >> 3, c = i & 7;
        uint32_t d = bB + r * 128 + ((c ^ ((r & 3) << 1)) << 4);
        cp16(d, Bp + (size_t)r * ldB + k0 + c * 4);
    }
}

__device__ __forceinline__ void compute_stage(uint32_t stbase,
                                              float acc[4][8][4],
                                              int lane, int wm, int wn) {
    uint32_t aB = stbase, bB = stbase + A_ST_BYTES;
    int qid = lane >> 2, quad = lane & 3;
    int sw = (qid & 3) << 1;
    int hh = quad >> 1, inner = (quad & 1) << 3;
    uint32_t aRow = aB + (wm + qid) * 128;
    uint32_t bRow = bB + (wn + qid) * 128;

    #pragma unroll
    for (int s = 0; s < 4; ++s) {               // 4 k8-steps per stage
        int cb = s * 2;
        uint32_t ct = (uint32_t)((((cb + hh) ^ sw) << 4) | inner);
        uint32_t a[4][4];
        #pragma unroll
        for (int mt = 0; mt < 4; ++mt) {
            uint32_t base = aRow + mt * (16 * 128) + ct;
            lds64(a[mt][0], a[mt][2], base);            // rows m   : (a0,a2)
            lds64(a[mt][1], a[mt][3], base + 8 * 128);  // rows m+8 : (a1,a3)
        }
        uint32_t bq[8][2];
        #pragma unroll
        for (int nt = 0; nt < 8; ++nt)
            lds64(bq[nt][0], bq[nt][1], bRow + nt * (8 * 128) + ct);
        #pragma unroll
        for (int mt = 0; mt < 4; ++mt)
            #pragma unroll
            for (int nt = 0; nt < 8; ++nt)
                mma_tf32(acc[mt][nt], a[mt], bq[nt]);
    }
}

template<int NSEG, int SPS>
__device__ __forceinline__ void gemm_pipeline(uint32_t sb,
                                              const float* const (&As)[NSEG],
                                              const float* const (&Bs)[NSEG],
                                              int ldA, int ldB,
                                              float acc[4][8][4],
                                              int tid, int lane, int wm, int wn) {
    const int S = NSEG * SPS;
    #pragma unroll
    for (int s = 0; s < 3; ++s) {
        int seg = s / SPS;
        load_stage(sb + s * ST_BYTES, As[seg], Bs[seg], (s % SPS) * KC, ldA, ldB, tid);
        cp_commit();
    }
    for (int it = 0; it < S; ++it) {
        cp_wait2();
        __syncthreads();
        int nx = it + 3;
        if (nx < S) {
            int seg = nx / SPS;
            load_stage(sb + (nx & 3) * ST_BYTES, As[seg], Bs[seg],
                       (nx % SPS) * KC, ldA, ldB, tid);
        }
        cp_commit();
        compute_stage(sb + (it & 3) * ST_BYTES, acc, lane, wm, wn);
    }
}

// ---------------------------------------------------------------------------
// GEMM1: h[bz] = tf32( w * gelu(x[b] @ W1[e] + b1[e]) ), FF-permuted store
// grid (FF/BN=32, T/BM=8, B*K=16)
// ---------------------------------------------------------------------------
__global__ void __launch_bounds__(NTH, 1) gemm1_kernel(const float* __restrict__ b1) {
    extern __shared__ __align__(1024) char smem[];
    uint32_t sb = smem_u32(smem);
    int tid = threadIdx.x, lane = tid & 31, wid = tid >> 5;
    int wm = (wid & 3) * 64, wn = (wid >> 2) * 64;
    int qid = lane >> 2, quad = lane & 3;

    int bz = blockIdx.z, b = bz >> 1, e = g_idx[bz];
    float wgt = g_w[bz];
    int m0 = blockIdx.y * BM, n0 = blockIdx.x * BN;

    const float* As[1] = { g_xt + ((size_t)b * T_ + m0) * D_ };
    const float* Bs[1] = { g_w1t + ((size_t)e * FF_ + n0) * D_ };

    float acc[4][8][4];
    #pragma unroll
    for (int i = 0; i < 4; ++i)
        #pragma unroll
        for (int j = 0; j < 8; ++j)
            #pragma unroll
            for (int l = 0; l < 4; ++l) acc[i][j][l] = 0.0f;

    gemm_pipeline<1, D_ / KC>(sb, As, Bs, D_, D_, acc, tid, lane, wm, wn);

    // Epilogue: bias + exact gelu + weight, tf32 round, permuted FF index
    const float* bias = b1 + (size_t)e * FF_;
    float* H = g_h + (size_t)bz * T_ * FF_;
    int p0 = ((quad & 1) << 2) | (quad >> 1);   // pos3(quad*2); pos of col+1 = p0+2

    #pragma unroll
    for (int mt = 0; mt < 4; ++mt) {
        int r0 = m0 + wm + mt * 16 + qid;
        #pragma unroll
        for (int half = 0; half < 2; ++half) {
            size_t rowb = (size_t)(r0 + half * 8) * FF_;
            #pragma unroll
            for (int nt = 0; nt < 8; ++nt) {
                int fb = n0 + wn + nt * 8;          // 8-aligned group base
                int f0 = fb + quad * 2;
                float v0 = acc[mt][nt][half * 2 + 0] + bias[f0];
                float v1 = acc[mt][nt][half * 2 + 1] + bias[f0 + 1];
                v0 = 0.5f * v0 * (1.0f + erff(v0 * 0.70710678118654752440f));
                v1 = 0.5f * v1 * (1.0f + erff(v1 * 0.70710678118654752440f));
                H[rowb + fb + p0]     = tf32r(wgt * v0);
                H[rowb + fb + p0 + 2] = tf32r(wgt * v1);
            }
        }
    }
}

// ---------------------------------------------------------------------------
// GEMM2: out[b] = sum_k h[b,k] @ W2[e_k] + sum_k w_k*b2[e_k]
// grid (D/BN=8, T/BM=8, B=8)
// ---------------------------------------------------------------------------
__global__ void __launch_bounds__(NTH, 1) gemm2_kernel(const float* __restrict__ b2,
                                                       float* __restrict__ out) {
    extern __shared__ __align__(1024) char smem[];
    uint32_t sb = smem_u32(smem);
    int tid = threadIdx.x, lane = tid & 31, wid = tid >> 5;
    int wm = (wid & 3) * 64, wn = (wid >> 2) * 64;
    int qid = lane >> 2, quad = lane & 3;

    int b = blockIdx.z;
    int m0 = blockIdx.y * BM, n0 = blockIdx.x * BN;
    int e0 = g_idx[b * K_ + 0], e1 = g_idx[b * K_ + 1];
    float w0 = g_w[b * K_ + 0], w1 = g_w[b * K_ + 1];

    const float* As[2] = {
        g_h + ((size_t)(b * K_ + 0) * T_ + m0) * FF_,
        g_h + ((size_t)(b * K_ + 1) * T_ + m0) * FF_
    };
    const float* Bs[2] = {
        g_w2t + ((size_t)e0 * D_ + n0) * FF_,
        g_w2t + ((size_t)e1 * D_ + n0) * FF_
    };

    float acc[4][8][4];
    #pragma unroll
    for (int i = 0; i < 4; ++i)
        #pragma unroll
        for (int j = 0; j < 8; ++j)
            #pragma unroll
            for (int l = 0; l < 4; ++l) acc[i][j][l] = 0.0f;

    gemm_pipeline<2, FF_ / KC>(sb, As, Bs, FF_, FF_, acc, tid, lane, wm, wn);

    const float* bias0 = b2 + (size_t)e0 * D_;
    const float* bias1 = b2 + (size_t)e1 * D_;
    float* O = out + (size_t)b * T_ * D_;

    #pragma unroll
    for (int mt = 0; mt < 4; ++mt) {
        int r0 = m0 + wm + mt * 16 + qid;
        #pragma unroll
        for (int half = 0; half < 2; ++half) {
            size_t rowb = (size_t)(r0 + half * 8) * D_;
            #pragma unroll
            for (int nt = 0; nt < 8; ++nt) {
                int c0 = n0 + wn + nt * 8 + quad * 2;
                float cb0 = w0 * bias0[c0]     + w1 * bias1[c0];
                float cb1 = w0 * bias0[c0 + 1] + w1 * bias1[c0 + 1];
                float2 v = make_float2(acc[mt][nt][half * 2 + 0] + cb0,
                                       acc[mt][nt][half * 2 + 1] + cb1);
                *(float2*)(O + rowb + c0) = v;
            }
        }
    }
}

// ---------------------------------------------------------------------------
// Launch
// ---------------------------------------------------------------------------
extern "C" void kernel_launch(void* const* d_in, const int* in_sizes, int n_in,
                              void* d_out, int out_size) {
    (void)in_sizes; (void)n_in; (void)out_size;
    const float* x  = (const float*)d_in[0];
    const float* Wr = (const float*)d_in[1];
    const float* W1 = (const float*)d_in[2];
    const float* b1 = (const float*)d_in[3];
    const float* W2 = (const float*)d_in[4];
    const float* b2 = (const float*)d_in[5];
    float* out = (float*)d_out;

    cudaFuncSetAttribute(gemm1_kernel, cudaFuncAttributeMaxDynamicSharedMemorySize, SMEM_TOTAL);
    cudaFuncSetAttribute(gemm2_kernel, cudaFuncAttributeMaxDynamicSharedMemorySize, SMEM_TOTAL);

    pool_kernel<<<dim3(D_ / 256, B_), 256>>>(x);
    route_kernel<<<1, 64>>>(Wr);
    convert_x_kernel<<<(B_ * T_ * D_) / (8 * NTH), NTH>>>(x);
    transpose_w1_kernel<<<dim3(FF_ / 32, D_ / 32, E_), dim3(32, 8)>>>(W1);
    transpose_w2_kernel<<<dim3(D_ / 32, FF_ / 32, E_), dim3(32, 8)>>>(W2);

    gemm1_kernel<<<dim3(FF_ / BN, T_ / BM, B_ * K_), NTH, SMEM_TOTAL>>>(b1);
    gemm2_kernel<<<dim3(D_ / BN, T_ / BM, B_), NTH, SMEM_TOTAL>>>(b2, out);
}

// round 4
// speedup vs baseline: 3.0380x; 1.8107x over previous
#include <cuda_runtime.h>
#include <cuda_fp16.h>
#include <math.h>
#include <stdint.h>

// Problem constants
#define B_  8
#define T_  2048
#define D_  1024
#define FF_ 4096
#define E_  8
#define K_  2

// GEMM tiling
#define BM 256
#define BN 128
#define KC 64            // fp16 k per stage (128B rows)
#define NTH 256

#define A_ST_BYTES (BM * 128)                 // 32KB
#define B_ST_BYTES (BN * 128)                 // 16KB
#define ST_BYTES   (A_ST_BYTES + B_ST_BYTES)  // 48KB
#define SMEM_TOTAL (4 * ST_BYTES)             // 192KB

// ---------------------------------------------------------------------------
// Device-global scratch
// ---------------------------------------------------------------------------
__device__ float g_pooled[B_ * D_];
__device__ int   g_idx[B_ * K_];
__device__ float g_w[B_ * K_];
__device__ __align__(256) __half g_xt[B_ * T_ * D_];               // x fp16, k16-perm
__device__ __align__(256) __half g_w1t[(size_t)E_ * FF_ * D_];     // [E][FF][Dperm]
__device__ __align__(256) __half g_w2t[(size_t)E_ * D_ * FF_];     // [E][D][FFperm]
__device__ __align__(256) __half g_h[(size_t)B_ * K_ * T_ * FF_];  // h fp16, FF-perm

// ---------------------------------------------------------------------------
// Helpers
// ---------------------------------------------------------------------------
__device__ __forceinline__ uint32_t smem_u32(const void* p) {
    uint32_t a;
    asm("{ .reg .u64 t; cvta.to.shared.u64 t, %1; cvt.u32.u64 %0, t; }"
        : "=r"(a) : "l"(p));
    return a;
}

// position of k-index c (0..15) in permuted order [0,1,8,9, 2,3,10,11, 4,5,12,13, 6,7,14,15]
__device__ __forceinline__ int pos16(int c) {
    return ((c & 6) << 1) | ((c & 8) >> 2) | (c & 1);
}

__device__ __forceinline__ void cp16(uint32_t dst, const void* src) {
    asm volatile("cp.async.cg.shared.global [%0], [%1], 16;" :: "r"(dst), "l"(src));
}
__device__ __forceinline__ void cp_commit() {
    asm volatile("cp.async.commit_group;" ::: "memory");
}
__device__ __forceinline__ void cp_wait2() {
    asm volatile("cp.async.wait_group 2;" ::: "memory");
}

__device__ __forceinline__ void lds64(uint32_t& x, uint32_t& y, uint32_t a) {
    asm volatile("ld.shared.v2.b32 {%0,%1}, [%2];" : "=r"(x), "=r"(y) : "r"(a));
}

__device__ __forceinline__ void mma_f16(float c[4], const uint32_t a[4], const uint32_t b[2]) {
    asm volatile(
        "mma.sync.aligned.m16n8k16.row.col.f32.f16.f16.f32 "
        "{%0,%1,%2,%3},{%4,%5,%6,%7},{%8,%9},{%0,%1,%2,%3};\n"
        : "+f"(c[0]), "+f"(c[1]), "+f"(c[2]), "+f"(c[3])
        : "r"(a[0]), "r"(a[1]), "r"(a[2]), "r"(a[3]), "r"(b[0]), "r"(b[1]));
}

// ---------------------------------------------------------------------------
// Routing
// ---------------------------------------------------------------------------
__global__ void pool_kernel(const float* __restrict__ x) {
    int b = blockIdx.y;
    int d = blockIdx.x * 256 + threadIdx.x;
    const float* p = x + (size_t)b * T_ * D_ + d;
    float s = 0.0f;
    for (int t = 0; t < T_; ++t) s += p[(size_t)t * D_];
    g_pooled[b * D_ + d] = s * (1.0f / (float)T_);
}

__global__ void route_kernel(const float* __restrict__ Wr) {
    __shared__ float lg[B_ * E_];
    int tid = threadIdx.x;
    if (tid < B_ * E_) {
        int b = tid / E_, e = tid % E_;
        float s = 0.0f;
        for (int d = 0; d < D_; ++d) s += g_pooled[b * D_ + d] * Wr[d * E_ + e];
        lg[tid] = s;
    }
    __syncthreads();
    if (tid < B_) {
        float best = -1e30f; int bi = 0;
        for (int e = 0; e < E_; ++e) {
            float v = lg[tid * E_ + e];
            if (v > best) { best = v; bi = e; }
        }
        float sec = -1e30f; int si = 0;
        for (int e = 0; e < E_; ++e) {
            if (e == bi) continue;
            float v = lg[tid * E_ + e];
            if (v > sec) { sec = v; si = e; }
        }
        float e1 = expf(sec - best);
        float inv = 1.0f / (1.0f + e1);
        g_idx[tid * K_ + 0] = bi;
        g_idx[tid * K_ + 1] = si;
        g_w[tid * K_ + 0] = inv;
        g_w[tid * K_ + 1] = e1 * inv;
    }
}

// ---------------------------------------------------------------------------
// Prep: fp16 convert + k16 permute (and transpose for weights)
// ---------------------------------------------------------------------------
__global__ void convert_x_kernel(const float* __restrict__ x) {
    size_t gi = (size_t)blockIdx.x * NTH + threadIdx.x;   // one k16 group / thread
    const float4* p = (const float4*)(x + gi * 16);
    float in[16];
    #pragma unroll
    for (int q = 0; q < 4; ++q) {
        float4 v = p[q];
        in[q * 4 + 0] = v.x; in[q * 4 + 1] = v.y;
        in[q * 4 + 2] = v.z; in[q * 4 + 3] = v.w;
    }
    __align__(16) __half o[16];
    #pragma unroll
    for (int c = 0; c < 16; ++c) o[pos16(c)] = __float2half(in[c]);
    uint4* q = (uint4*)(g_xt + gi * 16);
    q[0] = ((const uint4*)o)[0];
    q[1] = ((const uint4*)o)[1];
}

// src [z][R][C] fp32 -> dst [z][C][Rperm16] fp16
__device__ __forceinline__ void transpose_body(const float* __restrict__ src,
                                               __half* __restrict__ dst,
                                               int R, int C) {
    __shared__ float t[32][33];
    int z = blockIdx.z;
    const float* s = src + (size_t)z * R * C;
    int c0 = blockIdx.x * 32, r0 = blockIdx.y * 32;
    int tx = threadIdx.x, ty = threadIdx.y;
    #pragma unroll
    for (int j = 0; j < 32; j += 8)
        t[ty + j][tx] = s[(size_t)(r0 + ty + j) * C + c0 + tx];
    __syncthreads();
    size_t ob = (size_t)z * R * C;
    int rp = r0 + (tx & ~15) + pos16(tx & 15);
    #pragma unroll
    for (int j = 0; j < 32; j += 8) {
        float v = t[tx][ty + j];
        dst[ob + (size_t)(c0 + ty + j) * R + rp] = __float2half(v);
    }
}

__global__ void transpose_w1_kernel(const float* __restrict__ W1) {
    transpose_body(W1, g_w1t, D_, FF_);   // [E][D][FF] -> [E][FF][Dperm]
}
__global__ void transpose_w2_kernel(const float* __restrict__ W2) {
    transpose_body(W2, g_w2t, FF_, D_);   // [E][FF][D] -> [E][D][FFperm]
}

// ---------------------------------------------------------------------------
// GEMM core: 4-stage cp.async pipeline, fp16 mma.sync m16n8k16, fp32 acc
// CTA 256x128, 8 warps 4(M)x2(N), warp tile 64x64.
// smem rows 128B (64 fp16), 16B chunks swizzled chunk ^= (row&3)<<1.
// k16 groups pre-permuted in gmem so each lane's fragment pairs are 8B.
// ---------------------------------------------------------------------------
__device__ __forceinline__ void load_stage(uint32_t stbase,
                                           const __half* __restrict__ A,
                                           const __half* __restrict__ Bp,
                                           int k0, int ldA, int ldB, int tid) {
    uint32_t aB = stbase, bB = stbase + A_ST_BYTES;
    #pragma unroll
    for (int j = 0; j < 8; ++j) {               // A: 2048 16B-chunks
        int i = tid + j * NTH;
        int r = i >> 3, c = i & 7;
        uint32_t d = aB + r * 128 + ((c ^ ((r & 3) << 1)) << 4);
        cp16(d, A + (size_t)r * ldA + k0 + c * 8);
    }
    #pragma unroll
    for (int j = 0; j < 4; ++j) {               // B: 1024 chunks
        int i = tid + j * NTH;
        int r = i >> 3, c = i & 7;
        uint32_t d = bB + r * 128 + ((c ^ ((r & 3) << 1)) << 4);
        cp16(d, Bp + (size_t)r * ldB + k0 + c * 8);
    }
}

__device__ __forceinline__ void compute_stage(uint32_t stbase,
                                              float acc[4][8][4],
                                              int lane, int wm, int wn) {
    uint32_t aB = stbase, bB = stbase + A_ST_BYTES;
    int g = lane >> 2, t = lane & 3;
    int sw = (g & 3) << 1;
    uint32_t aRow = aB + (wm + g) * 128;
    uint32_t bRow = bB + (wn + g) * 128;

    #pragma unroll
    for (int kg = 0; kg < 4; ++kg) {            // 4 k16-steps per stage
        uint32_t ct = (uint32_t)(((((kg << 1) + (t >> 1)) ^ sw) << 4) | ((t & 1) << 3));
        uint32_t a[4][4];
        #pragma unroll
        for (int mt = 0; mt < 4; ++mt) {
            uint32_t base = aRow + mt * (16 * 128) + ct;
            lds64(a[mt][0], a[mt][2], base);            // row g   : (a0,a2)
            lds64(a[mt][1], a[mt][3], base + 8 * 128);  // row g+8 : (a1,a3)
        }
        uint32_t bq[8][2];
        #pragma unroll
        for (int nt = 0; nt < 8; ++nt)
            lds64(bq[nt][0], bq[nt][1], bRow + nt * (8 * 128) + ct);
        #pragma unroll
        for (int mt = 0; mt < 4; ++mt)
            #pragma unroll
            for (int nt = 0; nt < 8; ++nt)
                mma_f16(acc[mt][nt], a[mt], bq[nt]);
    }
}

template<int NSEG, int SPS>
__device__ __forceinline__ void gemm_pipeline(uint32_t sb,
                                              const __half* const (&As)[NSEG],
                                              const __half* const (&Bs)[NSEG],
                                              int ldA, int ldB,
                                              float acc[4][8][4],
                                              int tid, int lane, int wm, int wn) {
    const int S = NSEG * SPS;
    #pragma unroll
    for (int s = 0; s < 3; ++s) {
        int seg = s / SPS;
        load_stage(sb + s * ST_BYTES, As[seg], Bs[seg], (s % SPS) * KC, ldA, ldB, tid);
        cp_commit();
    }
    for (int it = 0; it < S; ++it) {
        cp_wait2();
        __syncthreads();
        int nx = it + 3;
        if (nx < S) {
            int seg = nx / SPS;
            load_stage(sb + (nx & 3) * ST_BYTES, As[seg], Bs[seg],
                       (nx % SPS) * KC, ldA, ldB, tid);
        }
        cp_commit();
        compute_stage(sb + (it & 3) * ST_BYTES, acc, lane, wm, wn);
    }
}

// ---------------------------------------------------------------------------
// GEMM1: h[bz] = fp16( w * gelu(x[b] @ W1[e] + b1[e]) ), FF-permuted store
// grid (FF/BN=32, T/BM=8, B*K=16)
// ---------------------------------------------------------------------------
__global__ void __launch_bounds__(NTH, 1) gemm1_kernel(const float* __restrict__ b1) {
    extern __shared__ __align__(1024) char smem[];
    uint32_t sb = smem_u32(smem);
    int tid = threadIdx.x, lane = tid & 31, wid = tid >> 5;
    int wm = (wid & 3) * 64, wn = (wid >> 2) * 64;
    int g = lane >> 2, t = lane & 3;

    int bz = blockIdx.z, b = bz >> 1, e = g_idx[bz];
    float wgt = g_w[bz];
    int m0 = blockIdx.y * BM, n0 = blockIdx.x * BN;

    const __half* As[1] = { g_xt + ((size_t)b * T_ + m0) * D_ };
    const __half* Bs[1] = { g_w1t + ((size_t)e * FF_ + n0) * D_ };

    float acc[4][8][4];
    #pragma unroll
    for (int i = 0; i < 4; ++i)
        #pragma unroll
        for (int j = 0; j < 8; ++j)
            #pragma unroll
            for (int l = 0; l < 4; ++l) acc[i][j][l] = 0.0f;

    gemm_pipeline<1, D_ / KC>(sb, As, Bs, D_, D_, acc, tid, lane, wm, wn);

    // Epilogue: bias + exact gelu + weight, fp16 store with k16 perm over FF
    const float* bias = b1 + (size_t)e * FF_;
    __half* H = g_h + (size_t)bz * T_ * FF_;

    #pragma unroll
    for (int mt = 0; mt < 4; ++mt) {
        int r0 = m0 + wm + mt * 16 + g;
        #pragma unroll
        for (int half = 0; half < 2; ++half) {
            size_t rowb = (size_t)(r0 + half * 8) * FF_;
            #pragma unroll
            for (int nt = 0; nt < 8; ++nt) {
                int f0 = n0 + wn + nt * 8 + t * 2;      // natural column
                float v0 = acc[mt][nt][half * 2 + 0] + bias[f0];
                float v1 = acc[mt][nt][half * 2 + 1] + bias[f0 + 1];
                v0 = 0.5f * v0 * (1.0f + erff(v0 * 0.70710678118654752440f));
                v1 = 0.5f * v1 * (1.0f + erff(v1 * 0.70710678118654752440f));
                // permuted position within the 16-group spanned by nt pair
                int fb16 = n0 + wn + (nt & ~1) * 8;
                int p = 4 * t + 2 * (nt & 1);
                __half2 hv = __floats2half2_rn(wgt * v0, wgt * v1);
                *(__half2*)(H + rowb + fb16 + p) = hv;
            }
        }
    }
}

// ---------------------------------------------------------------------------
// GEMM2: out[b] = sum_k h[b,k] @ W2[e_k] + sum_k w_k*b2[e_k]
// grid (D/BN=8, T/BM=8, B=8)
// ---------------------------------------------------------------------------
__global__ void __launch_bounds__(NTH, 1) gemm2_kernel(const float* __restrict__ b2,
                                                       float* __restrict__ out) {
    extern __shared__ __align__(1024) char smem[];
    uint32_t sb = smem_u32(smem);
    int tid = threadIdx.x, lane = tid & 31, wid = tid >> 5;
    int wm = (wid & 3) * 64, wn = (wid >> 2) * 64;
    int g = lane >> 2, t = lane & 3;

    int b = blockIdx.z;
    int m0 = blockIdx.y * BM, n0 = blockIdx.x * BN;
    int e0 = g_idx[b * K_ + 0], e1 = g_idx[b * K_ + 1];
    float w0 = g_w[b * K_ + 0], w1 = g_w[b * K_ + 1];

    const __half* As[2] = {
        g_h + ((size_t)(b * K_ + 0) * T_ + m0) * FF_,
        g_h + ((size_t)(b * K_ + 1) * T_ + m0) * FF_
    };
    const __half* Bs[2] = {
        g_w2t + ((size_t)e0 * D_ + n0) * FF_,
        g_w2t + ((size_t)e1 * D_ + n0) * FF_
    };

    float acc[4][8][4];
    #pragma unroll
    for (int i = 0; i < 4; ++i)
        #pragma unroll
        for (int j = 0; j < 8; ++j)
            #pragma unroll
            for (int l = 0; l < 4; ++l) acc[i][j][l] = 0.0f;

    gemm_pipeline<2, FF_ / KC>(sb, As, Bs, FF_, FF_, acc, tid, lane, wm, wn);

    const float* bias0 = b2 + (size_t)e0 * D_;
    const float* bias1 = b2 + (size_t)e1 * D_;
    float* O = out + (size_t)b * T_ * D_;

    #pragma unroll
    for (int mt = 0; mt < 4; ++mt) {
        int r0 = m0 + wm + mt * 16 + g;
        #pragma unroll
        for (int half = 0; half < 2; ++half) {
            size_t rowb = (size_t)(r0 + half * 8) * D_;
            #pragma unroll
            for (int nt = 0; nt < 8; ++nt) {
                int c0 = n0 + wn + nt * 8 + t * 2;
                float cb0 = w0 * bias0[c0]     + w1 * bias1[c0];
                float cb1 = w0 * bias0[c0 + 1] + w1 * bias1[c0 + 1];
                float2 v = make_float2(acc[mt][nt][half * 2 + 0] + cb0,
                                       acc[mt][nt][half * 2 + 1] + cb1);
                *(float2*)(O + rowb + c0) = v;
            }
        }
    }
}

// ---------------------------------------------------------------------------
// Launch
// ---------------------------------------------------------------------------
extern "C" void kernel_launch(void* const* d_in, const int* in_sizes, int n_in,
                              void* d_out, int out_size) {
    (void)in_sizes; (void)n_in; (void)out_size;
    const float* x  = (const float*)d_in[0];
    const float* Wr = (const float*)d_in[1];
    const float* W1 = (const float*)d_in[2];
    const float* b1 = (const float*)d_in[3];
    const float* W2 = (const float*)d_in[4];
    const float* b2 = (const float*)d_in[5];
    float* out = (float*)d_out;

    cudaFuncSetAttribute(gemm1_kernel, cudaFuncAttributeMaxDynamicSharedMemorySize, SMEM_TOTAL);
    cudaFuncSetAttribute(gemm2_kernel, cudaFuncAttributeMaxDynamicSharedMemorySize, SMEM_TOTAL);

    pool_kernel<<<dim3(D_ / 256, B_), 256>>>(x);
    route_kernel<<<1, 64>>>(Wr);
    convert_x_kernel<<<(B_ * T_ * D_) / (16 * NTH), NTH>>>(x);
    transpose_w1_kernel<<<dim3(FF_ / 32, D_ / 32, E_), dim3(32, 8)>>>(W1);
    transpose_w2_kernel<<<dim3(D_ / 32, FF_ / 32, E_), dim3(32, 8)>>>(W2);

    gemm1_kernel<<<dim3(FF_ / BN, T_ / BM, B_ * K_), NTH, SMEM_TOTAL>>>(b1);
    gemm2_kernel<<<dim3(D_ / BN, T_ / BM, B_), NTH, SMEM_TOTAL>>>(b2, out);
}